// round 9
// baseline (speedup 1.0000x reference)
#include <cuda_runtime.h>
#include <math.h>

#define T    2048
#define F    1024
#define NB   64          // total batch
#define HB   32          // half batch
#define KSEL 20
#define WPB  2048        // warps (rows) per batch

// scratch (no allocs allowed) — zero-init; g_cnt reset by gather kernel
__device__ float g_mags[NB * T];
__device__ int   g_idx[NB * KSEL];
__device__ int   g_cnt[NB];

__device__ __forceinline__ void red_release_add(int* p, int v) {
    asm volatile("red.release.gpu.global.add.s32 [%0], %1;"
                 :: "l"(p), "r"(v) : "memory");
}
__device__ __forceinline__ int ld_acquire(const int* p) {
    int v;
    asm volatile("ld.acquire.gpu.global.b32 %0, [%1];"
                 : "=r"(v) : "l"(p) : "memory");
    return v;
}

// ---------- kernel 1: mag stream + inline per-batch top-K -----------------
// 16384 blocks; block = 8 rows (one warp per row). Normal blocks: mag store +
// ONE fire-and-forget REDG per warp, then exit — zero added latency on the
// block critical path (the R6-R8 mistake was a blocking atomic + 2 barriers).
// Block slice==255 of each batch additionally polls the counter and runs the
// warp-local top-20 + 8-way merge for its batch (overlapped for 63/64 batches).
__global__ void __launch_bounds__(256)
mag_topk_kernel(const float* __restrict__ feat,
                const float* __restrict__ scores,
                const float* __restrict__ mask_abn,
                const float* __restrict__ mask_nor,
                float* __restrict__ out) {
    int blk   = blockIdx.x;
    int batch = blk >> 8;
    int slice = blk & 255;
    int tid   = threadIdx.x;
    int lane  = tid & 31;
    int wid   = tid >> 5;

    // ---- mag: one warp per row, 8 float4 loads per lane ----
    {
        int t = slice * 8 + wid;
        const float4* row = (const float4*)(feat + ((size_t)batch * T + t) * F);
        float s = 0.f;
#pragma unroll
        for (int i = 0; i < 8; i++) {
            float4 v = row[lane + i * 32];
            s += v.x * v.x + v.y * v.y + v.z * v.z + v.w * v.w;
        }
#pragma unroll
        for (int o = 16; o; o >>= 1) s += __shfl_xor_sync(0xffffffffu, s, o);
        if (lane == 0) {
            g_mags[batch * T + t] = sqrtf(s);
            red_release_add(&g_cnt[batch], 1);   // fire-and-forget, cumulative
        }
    }

    if (slice != 255) return;                    // normal blocks retire here

    // ---- designated top-K block for this batch ----
    __shared__ float s_wv[8][21];
    __shared__ int   s_wi[8][21];

    if (tid == 0) {
        while (ld_acquire(&g_cnt[batch]) < WPB) __nanosleep(32);
    }
    __syncthreads();

    int r = (batch >= HB) ? (batch - HB) : (batch + HB);   // output row
    const float* mask = (batch >= HB) ? mask_abn + (size_t)(batch - HB) * T
                                      : mask_nor + (size_t)batch * T;
    const float inv = 1.0f / 0.9f;               // 1/(1-P)
    float v[8];
#pragma unroll
    for (int j = 0; j < 8; j++) {
        int t = wid * 256 + j * 32 + lane;       // warp owns contiguous 256
        float d = (mask[t] > 0.1f) ? inv : 0.0f;
        v[j] = __ldcg(&g_mags[batch * T + t]) * d;   // bypass L1 (cross-SM)
    }

    // 20 warp-local rounds, zero block syncs
    for (int k = 0; k < KSEL; k++) {
        float bv = -1.0f; int bi = 1 << 30;
#pragma unroll
        for (int j = 0; j < 8; j++) {
            if (v[j] > bv) { bv = v[j]; bi = wid * 256 + j * 32 + lane; }
        }
#pragma unroll
        for (int o = 16; o; o >>= 1) {
            float ov = __shfl_xor_sync(0xffffffffu, bv, o);
            int   oi = __shfl_xor_sync(0xffffffffu, bi, o);
            if (ov > bv || (ov == bv && oi < bi)) { bv = ov; bi = oi; }
        }
        if (lane == 0) { s_wv[wid][k] = bv; s_wi[wid][k] = bi; }
        int local = bi - wid * 256;              // remove winner
        if ((local & 31) == lane) v[local >> 5] = -1.0f;
    }
    if (lane == 0) { s_wv[wid][20] = -2.0f; s_wi[wid][20] = 1 << 30; }
    __syncthreads();

    // warp 0: merge 8 descending lists of 20 (lanes 0..7 hold list heads)
    if (wid == 0) {
        int   p  = 0;
        float hv = (lane < 8) ? s_wv[lane][0] : -3.0f;
        int   hi = (lane < 8) ? s_wi[lane][0] : (1 << 30);
        int my_idx = 0;
        for (int k = 0; k < KSEL; k++) {
            float fv = hv; int fi = hi;
#pragma unroll
            for (int o = 4; o; o >>= 1) {
                float ov = __shfl_xor_sync(0xffffffffu, fv, o);
                int   oi = __shfl_xor_sync(0xffffffffu, fi, o);
                if (ov > fv || (ov == fv && oi < fi)) { fv = ov; fi = oi; }
            }
            fi = __shfl_sync(0xffffffffu, fi, 0);        // broadcast winner
            if (lane == k) my_idx = fi;
            if (lane < 8 && hi == fi) {                  // advance that list
                p++; hv = s_wv[lane][p]; hi = s_wi[lane][p];
            }
        }
        // indices + score mean (one parallel load pass)
        float sc = 0.f;
        if (lane < KSEL) {
            g_idx[r * KSEL + lane] = my_idx;
            sc = scores[(size_t)batch * T + my_idx];
        }
#pragma unroll
        for (int o = 16; o; o >>= 1) sc += __shfl_xor_sync(0xffffffffu, sc, o);
        if (lane == 0) out[r] = sc / (float)KSEL;
    }
}

// ---------- kernel 2: gather (wide, 1280 blocks) + counter reset ----------
// Launch boundary provides visibility of g_idx (and flushes L1), so this is
// a plain gather — no flags, no spinning.
__global__ void gather_kernel(const float* __restrict__ feat,
                              float* __restrict__ out) {
    int blk = blockIdx.x;
    int row = blk / KSEL;            // output row 0..63 (abn rows first)
    int k   = blk % KSEL;
    int batch = (row < HB) ? (HB + row) : (row - HB);
    int idx = g_idx[row * KSEL + k];
    const float4* src = (const float4*)(feat + ((size_t)batch * T + idx) * F);
    float4* dst = (float4*)(out + 64 + ((size_t)row * KSEL + k) * F);
    dst[threadIdx.x] = src[threadIdx.x];

    // replay-safe: reset batch counters for the next graph replay
    if (blk < NB && threadIdx.x == 0) g_cnt[blk] = 0;
}

extern "C" void kernel_launch(void* const* d_in, const int* in_sizes, int n_in,
                              void* d_out, int out_size) {
    const float* feat   = (const float*)d_in[0];
    const float* scores = (const float*)d_in[1];
    const float* mabn   = (const float*)d_in[2];
    const float* mnor   = (const float*)d_in[3];
    float* out = (float*)d_out;

    mag_topk_kernel<<<NB * 256, 256>>>(feat, scores, mabn, mnor, out);
    gather_kernel<<<NB * KSEL, 256>>>(feat, out);
}

// round 10
// speedup vs baseline: 1.9724x; 1.9724x over previous
#include <cuda_runtime.h>
#include <math.h>

#define T    2048
#define F    1024
#define NB   64          // total batch
#define HB   32          // half batch
#define KSEL 20

// scratch (no allocs allowed)
__device__ float g_mags[NB * T];
__device__ int   g_idx[NB * KSEL];

// -------- kernel 1: per-(b,t) L2 norm over feature dim --------
// one warp per row; 8 float4 loads per lane, fully coalesced. HBM-bound
// at ~6.9 TB/s (86% of spec) — measured roofline. Untouched.
__global__ void mag_kernel(const float* __restrict__ feat) {
    int warp = (blockIdx.x * blockDim.x + threadIdx.x) >> 5;  // 0 .. 64*2048-1
    int lane = threadIdx.x & 31;
    const float4* row = (const float4*)(feat + (size_t)warp * F);
    float s = 0.f;
#pragma unroll
    for (int i = 0; i < 8; i++) {
        float4 v = row[lane + i * 32];
        s += v.x * v.x + v.y * v.y + v.z * v.z + v.w * v.w;
    }
#pragma unroll
    for (int o = 16; o; o >>= 1) s += __shfl_xor_sync(0xffffffffu, s, o);
    if (lane == 0) g_mags[warp] = sqrtf(s);
}

// -------- kernel 2: top-K + score mean (64 blocks) -------------------------
// Warp-local top-20 (zero block syncs) then single-warp 8-way sorted merge.
// One __syncthreads total. Stable (value desc, index asc) tie-break matches
// jax.lax.top_k. Validated in R8/R9 (rel_err 9.6e-8).
__global__ void __launch_bounds__(256)
topk_kernel(const float* __restrict__ scores,
            const float* __restrict__ mask_abn,
            const float* __restrict__ mask_nor,
            float* __restrict__ out) {
    __shared__ float s_wv[8][21];
    __shared__ int   s_wi[8][21];

    int b = blockIdx.x;
    int tid = threadIdx.x;
    int lane = tid & 31;
    int wid = tid >> 5;

    int batch;
    const float* mask;
    if (b < HB) { batch = HB + b; mask = mask_abn + (size_t)b * T; }
    else        { batch = b - HB; mask = mask_nor + (size_t)(b - HB) * T; }

    const float inv = 1.0f / 0.9f;   // 1/(1-P)
    float v[8];
#pragma unroll
    for (int j = 0; j < 8; j++) {
        int t = wid * 256 + j * 32 + lane;    // warp owns contiguous 256
        float d = (mask[t] > 0.1f) ? inv : 0.0f;
        v[j] = g_mags[batch * T + t] * d;
    }

    // 20 warp-local rounds, no block syncs
    for (int k = 0; k < KSEL; k++) {
        float bv = -1.0f; int bi = 1 << 30;
#pragma unroll
        for (int j = 0; j < 8; j++) {
            if (v[j] > bv) { bv = v[j]; bi = wid * 256 + j * 32 + lane; }
        }
#pragma unroll
        for (int o = 16; o; o >>= 1) {
            float ov = __shfl_xor_sync(0xffffffffu, bv, o);
            int   oi = __shfl_xor_sync(0xffffffffu, bi, o);
            if (ov > bv || (ov == bv && oi < bi)) { bv = ov; bi = oi; }
        }
        if (lane == 0) { s_wv[wid][k] = bv; s_wi[wid][k] = bi; }
        int local = bi - wid * 256;           // remove winner from registers
        if ((local & 31) == lane) v[local >> 5] = -1.0f;
    }
    if (lane == 0) { s_wv[wid][20] = -2.0f; s_wi[wid][20] = 1 << 30; }
    __syncthreads();

    // warp 0: merge 8 descending lists of 20 (lanes 0..7 hold list heads)
    if (wid == 0) {
        int   p  = 0;
        float hv = (lane < 8) ? s_wv[lane][0] : -3.0f;
        int   hi = (lane < 8) ? s_wi[lane][0] : (1 << 30);
        int my_idx = 0;
        for (int k = 0; k < KSEL; k++) {
            float fv = hv; int fi = hi;
#pragma unroll
            for (int o = 4; o; o >>= 1) {
                float ov = __shfl_xor_sync(0xffffffffu, fv, o);
                int   oi = __shfl_xor_sync(0xffffffffu, fi, o);
                if (ov > fv || (ov == fv && oi < fi)) { fv = ov; fi = oi; }
            }
            fi = __shfl_sync(0xffffffffu, fi, 0);       // broadcast winner
            if (lane == k) my_idx = fi;
            if (lane < 8 && hi == fi) {                 // advance that list
                p++; hv = s_wv[lane][p]; hi = s_wi[lane][p];
            }
        }
        // indices + score mean (one parallel load pass)
        float sc = 0.f;
        if (lane < KSEL) {
            g_idx[b * KSEL + lane] = my_idx;
            sc = scores[(size_t)batch * T + my_idx];
        }
#pragma unroll
        for (int o = 16; o; o >>= 1) sc += __shfl_xor_sync(0xffffffffu, sc, o);
        if (lane == 0) out[b] = sc / (float)KSEL;   // [0,32)=abn, [32,64)=nor
    }
}

// -------- kernel 3: gather, grid-stride with 4 float4s per thread ---------
// 1280 rows x 4KB = 327680 float4 elements. 320 blocks x 256 threads x 4
// independent copies each -> MLP=4 per thread (R9's 1-per-thread version was
// latency-bound at 7.5us).
#define GV4   (NB * KSEL * (F / 4))     // total float4 elements: 327680
#define GTHREADS (320 * 256)

__global__ void __launch_bounds__(256)
gather_kernel(const float* __restrict__ feat,
              float* __restrict__ out) {
    int gid = blockIdx.x * 256 + threadIdx.x;
    float4* dst = (float4*)(out + 64);
#pragma unroll
    for (int i = 0; i < 4; i++) {
        int e   = gid + i * GTHREADS;        // element id
        int row = e >> 8;                    // / (F/4=256): output row*KSEL+k
        int c   = e & 255;                   // float4 within the row
        int orow = row / KSEL;               // 0..63 (abn rows first)
        int k    = row % KSEL;
        int batch = (orow < HB) ? (HB + orow) : (orow - HB);
        int idx = g_idx[orow * KSEL + k];
        const float4* src = (const float4*)(feat + ((size_t)batch * T + idx) * F);
        dst[(size_t)row * 256 + c] = src[c];
    }
}

extern "C" void kernel_launch(void* const* d_in, const int* in_sizes, int n_in,
                              void* d_out, int out_size) {
    const float* feat   = (const float*)d_in[0];
    const float* scores = (const float*)d_in[1];
    const float* mabn   = (const float*)d_in[2];
    const float* mnor   = (const float*)d_in[3];
    float* out = (float*)d_out;

    mag_kernel<<<(NB * T) / 8, 256>>>(feat);
    topk_kernel<<<NB, 256>>>(scores, mabn, mnor, out);
    gather_kernel<<<320, 256>>>(feat, out);
}